// round 17
// baseline (speedup 1.0000x reference)
#include <cuda_runtime.h>
#include <cuda_bf16.h>
#include <math.h>

#define NUM_SEG 16
#define CHAN 128
#define HID 32

// Pass-1: 128 thr (4 warps), NO smem accumulators -> reg-limited.
// launch_bounds(128,5) caps regs at 102 (64 accum + ~35 working). One wave:
#define NBLK1 740          // 148 SMs * 5 blocks
#define THR1 128

// Modulate: 8 blocks/SM single wave
#define NBLK3 1184
#define THR3 256

// Zero-initialized at module load; reduce_mlp re-zeroes after consuming, so
// the zero invariant holds across every graph replay (same work every call).
__device__ float g_sum[NUM_SEG * CHAN];   // atomic accumulators
__device__ float g_cnt[NUM_SEG];          // atomic count accumulators
__device__ float g_gate[NUM_SEG * CHAN];  // final gates

// ---- packed f32x2 helpers (sm_103a) --------------------------------------
__device__ __forceinline__ unsigned long long fadd2(unsigned long long a,
                                                    unsigned long long b) {
    unsigned long long r;
    asm("add.rn.f32x2 %0, %1, %2;" : "=l"(r) : "l"(a), "l"(b));
    return r;
}
__device__ __forceinline__ unsigned long long fmul2(unsigned long long a,
                                                    unsigned long long b) {
    unsigned long long r;
    asm("mul.rn.f32x2 %0, %1, %2;" : "=l"(r) : "l"(a), "l"(b));
    return r;
}

struct F4 { unsigned long long lo, hi; };  // float4 as 2x f32x2

__device__ __forceinline__ F4 ld_f4_cs(const F4* p) {
    F4 r;
    asm("ld.global.cs.v4.b32 {%0,%1,%2,%3}, [%4];"
        : "=r"(((unsigned*)&r)[0]), "=r"(((unsigned*)&r)[1]),
          "=r"(((unsigned*)&r)[2]), "=r"(((unsigned*)&r)[3])
        : "l"(p));
    return r;
}

// ---------------------------------------------------------------------------
// Kernel 1: segment sums with REGISTER accumulators. Lane L owns channels
// [4L,4L+3] for all 16 segments (16 x F4 = 64 regs). The row's segment is
// warp-uniform -> 16-case switch (uniform BRX, zero L1 traffic) replaces the
// smem LDS/STS RMW: L1 cost drops 12 -> 4 wavefronts/row. Epilogue REDs the
// registers straight into g_sum.
// ---------------------------------------------------------------------------
#define ACCUM_CASE(K) case K: \
    a##K.lo = fadd2(a##K.lo, v.lo); a##K.hi = fadd2(a##K.hi, v.hi); break;

__global__ void __launch_bounds__(THR1, 5) seg_sum_kernel(
    const float* __restrict__ x, const int* __restrict__ idx, int N)
{
    const int tid  = threadIdx.x;
    const int lane = tid & 31;
    const int w    = tid >> 5;

    F4 a0{},a1{},a2{},a3{},a4{},a5{},a6{},a7{},
       a8{},a9{},a10{},a11{},a12{},a13{},a14{},a15{};

    const int gw = blockIdx.x * 4 + w;   // global warp id
    const int NW = NBLK1 * 4;            // total warps
    const F4* X = (const F4*)x;
    const int ngroups = N >> 2;          // groups of 4 rows (N % 4 == 0)

    int cnt = 0;
    for (int g = gw; g < ngroups; g += NW) {
        const int base = g << 2;
        int4 is = __ldg((const int4*)(idx + base));
        const size_t o = (size_t)base * 32 + lane;
        F4 v0 = ld_f4_cs(X + o);
        F4 v1 = ld_f4_cs(X + o + 32);
        F4 v2 = ld_f4_cs(X + o + 64);
        F4 v3 = ld_f4_cs(X + o + 96);

        cnt += (is.x == lane) + (is.y == lane) + (is.z == lane) + (is.w == lane);

        #pragma unroll
        for (int q = 0; q < 4; q++) {
            int s = (q == 0) ? is.x : (q == 1) ? is.y : (q == 2) ? is.z : is.w;
            F4 v = (q == 0) ? v0 : (q == 1) ? v1 : (q == 2) ? v2 : v3;
            switch (s) {
                ACCUM_CASE(0)  ACCUM_CASE(1)  ACCUM_CASE(2)  ACCUM_CASE(3)
                ACCUM_CASE(4)  ACCUM_CASE(5)  ACCUM_CASE(6)  ACCUM_CASE(7)
                ACCUM_CASE(8)  ACCUM_CASE(9)  ACCUM_CASE(10) ACCUM_CASE(11)
                ACCUM_CASE(12) ACCUM_CASE(13) ACCUM_CASE(14) ACCUM_CASE(15)
            }
        }
    }
    // tail (N not multiple of 4)
    for (int r = (ngroups << 2) + gw; r < N; r += NW) {
        int s = __ldg(idx + r);
        F4 v = ld_f4_cs(X + (size_t)r * 32 + lane);
        cnt += (s == lane);
        switch (s) {
            ACCUM_CASE(0)  ACCUM_CASE(1)  ACCUM_CASE(2)  ACCUM_CASE(3)
            ACCUM_CASE(4)  ACCUM_CASE(5)  ACCUM_CASE(6)  ACCUM_CASE(7)
            ACCUM_CASE(8)  ACCUM_CASE(9)  ACCUM_CASE(10) ACCUM_CASE(11)
            ACCUM_CASE(12) ACCUM_CASE(13) ACCUM_CASE(14) ACCUM_CASE(15)
        }
    }

    // Epilogue: RED register accumulators into g_sum[seg*128 + 4*lane + j].
    float* dst = g_sum + lane * 4;
    #pragma unroll
    for (int s = 0; s < NUM_SEG; s++) {
        F4 a = (s==0)?a0:(s==1)?a1:(s==2)?a2:(s==3)?a3:(s==4)?a4:(s==5)?a5:
               (s==6)?a6:(s==7)?a7:(s==8)?a8:(s==9)?a9:(s==10)?a10:(s==11)?a11:
               (s==12)?a12:(s==13)?a13:(s==14)?a14:a15;
        float2 lo = *(float2*)&a.lo;
        float2 hi = *(float2*)&a.hi;
        atomicAdd(dst + s * CHAN + 0, lo.x);
        atomicAdd(dst + s * CHAN + 1, lo.y);
        atomicAdd(dst + s * CHAN + 2, hi.x);
        atomicAdd(dst + s * CHAN + 3, hi.y);
    }
    if (lane < NUM_SEG && cnt > 0)
        atomicAdd(&g_cnt[lane], (float)cnt);
}

// ---------------------------------------------------------------------------
// Kernel 2: SE MLP on the accumulated sums (8KB read), then RE-ZERO the
// accumulators (replay invariant). 16 blocks x 128 threads.
// ---------------------------------------------------------------------------
__global__ void __launch_bounds__(CHAN) reduce_mlp_kernel(
    const float* __restrict__ W1, const float* __restrict__ W2)
{
    const int s = blockIdx.x;
    const int c = threadIdx.x;

    __shared__ float s_pooled[CHAN];
    __shared__ float s_h[HID];

    float cnt = fmaxf(g_cnt[s], 1.0f);
    s_pooled[c] = g_sum[s * CHAN + c] / cnt;
    __syncthreads();

    // g_sum/g_cnt fully consumed above -> restore zero invariant now.
    g_sum[s * CHAN + c] = 0.f;
    if (c == 0) g_cnt[s] = 0.f;

    if (c < HID) {
        float acc = 0.f;
        #pragma unroll 8
        for (int k = 0; k < CHAN; k++)
            acc += s_pooled[k] * __ldg(W1 + c * CHAN + k);
        s_h[c] = fmaxf(acc, 0.f);
    }
    __syncthreads();

    float acc = 0.f;
    #pragma unroll
    for (int k = 0; k < HID; k++)
        acc += s_h[k] * __ldg(W2 + c * HID + k);
    g_gate[s * CHAN + c] = 1.0f / (1.0f + expf(-acc));
}

// ---------------------------------------------------------------------------
// Kernel 3: out = x * gate[idx] (measured at the mixed R/W DRAM cap ~80%).
// ---------------------------------------------------------------------------
__global__ void __launch_bounds__(THR3) modulate_kernel(
    const float* __restrict__ x, const int* __restrict__ idx,
    float* __restrict__ out, int N)
{
    __shared__ float4 s_gate[NUM_SEG * 32];  // 8KB

    for (int i = threadIdx.x; i < NUM_SEG * 32; i += THR3)
        s_gate[i] = ((const float4*)g_gate)[i];
    __syncthreads();

    const float4* X = (const float4*)x;
    float4* O = (float4*)out;
    const int total  = N * 32;
    const int stride = NBLK3 * THR3;

    #pragma unroll 4
    for (int i = blockIdx.x * THR3 + threadIdx.x; i < total; i += stride) {
        int row  = i >> 5;
        int lane = i & 31;
        int s = __ldg(idx + row);
        float4 v = __ldcs(X + i);
        float4 g = s_gate[s * 32 + lane];
        unsigned long long* vp = (unsigned long long*)&v;
        const unsigned long long* gp = (const unsigned long long*)&g;
        vp[0] = fmul2(vp[0], gp[0]);
        vp[1] = fmul2(vp[1], gp[1]);
        __stcs(O + i, v);
    }
}

// ---------------------------------------------------------------------------
extern "C" void kernel_launch(void* const* d_in, const int* in_sizes, int n_in,
                              void* d_out, int out_size)
{
    const float* x   = (const float*)d_in[0];
    const int*   idx = (const int*)d_in[1];
    const float* W1  = (const float*)d_in[2];
    const float* W2  = (const float*)d_in[3];
    float* out = (float*)d_out;

    const int N = in_sizes[1];  // number of points

    seg_sum_kernel<<<NBLK1, THR1>>>(x, idx, N);
    reduce_mlp_kernel<<<NUM_SEG, CHAN>>>(W1, W2);
    modulate_kernel<<<NBLK3, THR3>>>(x, idx, out, N);
}